// round 10
// baseline (speedup 1.0000x reference)
#include <cuda_runtime.h>
#include <cstdint>

// B=4, H=256, W=256 torus. mu-subsystem only. Persistent kernel with
// f32x2 packed math: lane = column PAIR. 128 blocks (1/SM) x 512 thr;
// 16 warps x (5 rows x 64 cols). Region 80r x 64c, interior 64r x 32c,
// T=8, 13 periods (12x8 + 4).
#define BHW 262144
#define NBLOCKS 128

typedef unsigned long long ull;

__device__ float  g_mu[2][BHW];
__device__ float  g_v [2][BHW];
__device__ float4 g_c [BHW];          // 0.01*(ex, ey, eu0, el1)
__device__ float2 g_ac[BHW];          // 0.01*(2*uw1, uw2*y)
__device__ unsigned g_bar;

// ---------------- packed f32x2 helpers ----------------
__device__ __forceinline__ ull pk(float lo, float hi) {
    ull r; asm("mov.b64 %0, {%1, %2};" : "=l"(r) : "f"(lo), "f"(hi)); return r;
}
__device__ __forceinline__ void upk(ull a, float& lo, float& hi) {
    asm("mov.b64 {%0, %1}, %2;" : "=f"(lo), "=f"(hi) : "l"(a));
}
__device__ __forceinline__ ull fma2(ull a, ull b, ull c) {
    ull d; asm("fma.rn.f32x2 %0, %1, %2, %3;" : "=l"(d) : "l"(a), "l"(b), "l"(c)); return d;
}
__device__ __forceinline__ ull add2(ull a, ull b) {
    ull d; asm("add.rn.f32x2 %0, %1, %2;" : "=l"(d) : "l"(a), "l"(b)); return d;
}
__device__ __forceinline__ ull clip2(ull a) {
    float lo, hi; upk(a, lo, hi);
    lo = fminf(fmaxf(lo, 0.0f), 63.0f);
    hi = fminf(fmaxf(hi, 0.0f), 63.0f);
    return pk(lo, hi);
}
__device__ __forceinline__ uint32_t smem_u32(const void* p) {
    uint32_t a;
    asm("{ .reg .u64 t; cvta.to.shared.u64 t, %1; cvt.u32.u64 %0, t; }"
        : "=r"(a) : "l"(p));
    return a;
}

#define K07 0x3F3333333F333333ULL   // (0.7f, 0.7f)

// ---------------- init ----------------
__global__ __launch_bounds__(256) void init_kernel(const float* __restrict__ y,
                                                   const float2* __restrict__ ew2,
                                                   const float2* __restrict__ un2) {
    const int p = blockIdx.x * 256 + threadIdx.x;
    const int base = p & ~65535;
    const int i    = p &  65535;
    const int row  = i & ~255;
    const int pu = base | ((i + 65280) & 65535);
    const int pl = base | row | ((i + 255) & 255);

    const float yv = y[p];
    const float2 e  = ew2[p];
    const float  eu = ew2[pu].x;
    const float  el = ew2[pl].y;
    const float2 u  = un2[p];

    g_mu[0][p] = yv;
    g_v [0][p] = 0.0f;
    g_c [p]    = make_float4(0.01f * e.x, 0.01f * e.y, 0.01f * eu, 0.01f * el);
    g_ac[p]    = make_float2(0.01f * 2.0f * u.x, 0.01f * u.y * yv);
    if (p == 0) g_bar = 0u;
}

// ---------------- persistent kernel ----------------
__global__ __launch_bounds__(512, 1) void persist_kernel(float* __restrict__ out) {
    __shared__ ull s_top[2][16][32];     // warp row-0 mu pairs, double-buffered
    __shared__ ull s_bot[2][16][32];     // warp row-4 mu pairs
    __shared__ unsigned long long s_mbar;

    const int lane = threadIdx.x & 31;
    const int w    = threadIdx.x >> 5;            // band 0..15 (5 rows each)
    const int blk  = blockIdx.x;                  // 4 img x 4 vtile x 8 htile
    const int base = (blk >> 5) << 16;
    const int tv   = (blk >> 3) & 3;
    const int th   = blk & 7;
    const int gc0  = (th * 32 - 16 + 2 * lane) & 255;   // even; pair never wraps
    const int r0   = tv * 64 - 8 + w * 5;

    const uint32_t mbar = smem_u32(&s_mbar);
    if (threadIdx.x == 0) {
        asm volatile("mbarrier.init.shared.b64 [%0], %1;" :: "r"(mbar), "r"(512) : "memory");
    }
    __syncthreads();

    // Packed per-row state. cz2[r] == cx2[r-1]; row 0 needs explicit cz0_2.
    ull mu2[5], v2[5], cx2[5], cy2[5], cw2[5], ax2[5], ay2[5], cz0_2;

    #pragma unroll
    for (int r = 0; r < 5; ++r) {
        const int p0 = base + (((r0 + r) & 255) << 8) + gc0;
        mu2[r] = *(const ull*)&g_mu[0][p0];
        v2[r]  = *(const ull*)&g_v[0][p0];
        const float4 c0 = g_c[p0], c1 = g_c[p0 + 1];
        cx2[r] = pk(c0.x, c1.x);
        cy2[r] = pk(c0.y, c1.y);
        cw2[r] = pk(c0.w, c1.w);
        if (r == 0) cz0_2 = pk(c0.z, c1.z);
        const float2 a0 = g_ac[p0], a1 = g_ac[p0 + 1];
        ax2[r] = pk(a0.x, a1.x);
        ay2[r] = pk(a0.y, a1.y);
    }

    unsigned target = 0;
    int phase = 0;

    for (int per = 0; per < 13; ++per) {
        const int TT = (per < 12) ? 8 : 4;

        s_top[0][w][lane] = mu2[0];
        s_bot[0][w][lane] = mu2[4];
        asm volatile("mbarrier.arrive.shared.b64 _, [%0];" :: "r"(mbar) : "memory");

        for (int it = 0; it < TT; ++it) {
            const int rb = it & 1;
            const ull old0 = mu2[0], old1 = mu2[1];
            const ull old3 = mu2[3], old4 = mu2[4];

            // ---- interior rows 1..3 (own old registers only) ----
            ull above = old0;
            #pragma unroll
            for (int r = 1; r < 4; ++r) {
                const ull cur = mu2[r];
                float clo, chi; upk(cur, clo, chi);
                const float phi = __shfl_up_sync(0xFFFFFFFFu, chi, 1);
                const float nlo = __shfl_down_sync(0xFFFFFFFFu, clo, 1);
                const ull left  = pk(phi, clo);
                const ull right = pk(chi, nlo);

                ull dmu = fma2(ax2[r], cur, ay2[r]);
                dmu = fma2(cx2[r], mu2[r + 1], dmu);       // below (still old)
                dmu = fma2(cy2[r], right, dmu);
                dmu = fma2(cx2[r - 1], above, dmu);
                dmu = fma2(cw2[r], left, dmu);

                v2[r] = fma2(K07, v2[r], dmu);
                above = cur;
                mu2[r] = clip2(add2(cur, v2[r]));
            }

            // ---- wait for this phase's boundary values ----
            {
                uint32_t done;
                asm volatile(
                    "{\n\t.reg .pred p;\n\t"
                    "mbarrier.try_wait.parity.acquire.cta.shared::cta.b64 p, [%1], %2;\n\t"
                    "selp.b32 %0, 1, 0, p;\n\t}"
                    : "=r"(done) : "r"(mbar), "r"(phase) : "memory");
                if (!done) {
                    asm volatile(
                        "{\n\t.reg .pred P1;\n\t"
                        "W_%=:\n\t"
                        "mbarrier.try_wait.parity.acquire.cta.shared::cta.b64 P1, [%0], %1, 0x989680;\n\t"
                        "@P1 bra.uni D_%=;\n\t"
                        "bra.uni W_%=;\n\t"
                        "D_%=:\n\t}"
                        :: "r"(mbar), "r"(phase) : "memory");
                }
                phase ^= 1;
            }

            const ull nb_above = (w > 0)  ? s_bot[rb][w - 1][lane] : old0;
            const ull nb_below = (w < 15) ? s_top[rb][w + 1][lane] : old4;

            // ---- row 0 ----
            {
                float clo, chi; upk(old0, clo, chi);
                const float phi = __shfl_up_sync(0xFFFFFFFFu, chi, 1);
                const float nlo = __shfl_down_sync(0xFFFFFFFFu, clo, 1);
                ull dmu = fma2(ax2[0], old0, ay2[0]);
                dmu = fma2(cx2[0], old1, dmu);
                dmu = fma2(cy2[0], pk(chi, nlo), dmu);
                dmu = fma2(cz0_2,  nb_above, dmu);
                dmu = fma2(cw2[0], pk(phi, clo), dmu);
                v2[0] = fma2(K07, v2[0], dmu);
                mu2[0] = clip2(add2(old0, v2[0]));
            }
            // ---- row 4 ----
            {
                float clo, chi; upk(old4, clo, chi);
                const float phi = __shfl_up_sync(0xFFFFFFFFu, chi, 1);
                const float nlo = __shfl_down_sync(0xFFFFFFFFu, clo, 1);
                ull dmu = fma2(ax2[4], old4, ay2[4]);
                dmu = fma2(cx2[4], nb_below, dmu);
                dmu = fma2(cy2[4], pk(chi, nlo), dmu);
                dmu = fma2(cx2[3], old3, dmu);
                dmu = fma2(cw2[4], pk(phi, clo), dmu);
                v2[4] = fma2(K07, v2[4], dmu);
                mu2[4] = clip2(add2(old4, v2[4]));
            }

            if (it < TT - 1) {
                s_top[rb ^ 1][w][lane] = mu2[0];
                s_bot[rb ^ 1][w][lane] = mu2[4];
                asm volatile("mbarrier.arrive.shared.b64 _, [%0];" :: "r"(mbar) : "memory");
            }
        }

        const int d = (per + 1) & 1;

        // Write exact interior: region rows 8..71 (global rows tv*64..+63),
        // lanes 8..23 (region cols 16..47).
        if (lane >= 8 && lane < 24) {
            #pragma unroll
            for (int r = 0; r < 5; ++r) {
                const int R = w * 5 + r;
                if (R >= 8 && R < 72) {
                    const int p0 = base + (((r0 + r) & 255) << 8) + gc0;
                    *(ull*)&g_mu[d][p0] = mu2[r];
                    *(ull*)&g_v [d][p0] = v2[r];
                    if (per == 12) *(ull*)&out[p0] = mu2[r];
                }
            }
        }

        if (per == 12) break;

        // ---- global period barrier (single counter) ----
        __threadfence();
        __syncthreads();
        target += NBLOCKS;
        if (threadIdx.x == 0) {
            atomicAdd(&g_bar, 1u);
            while (*((volatile unsigned*)&g_bar) < target) { }
            __threadfence();
        }
        __syncthreads();

        // Reload halo cells' mu,v (interior stays in registers).
        #pragma unroll
        for (int r = 0; r < 5; ++r) {
            const int R = w * 5 + r;
            const bool interior = (R >= 8) && (R < 72) && (lane >= 8) && (lane < 24);
            if (!interior) {
                const int p0 = base + (((r0 + r) & 255) << 8) + gc0;
                mu2[r] = *(const ull*)&g_mu[d][p0];
                v2[r]  = *(const ull*)&g_v[d][p0];
            }
        }
    }
}

// ---------------- launch ----------------
extern "C" void kernel_launch(void* const* d_in, const int* in_sizes, int n_in,
                              void* d_out, int out_size) {
    const float* y  = (const float*)d_in[0];
    const float* ew = (const float*)d_in[1];
    const float* un = (const float*)d_in[2];
    float* out = (float*)d_out;

    init_kernel<<<1024, 256>>>(y, (const float2*)ew, (const float2*)un);
    persist_kernel<<<NBLOCKS, 512>>>(out);
}

// round 11
// speedup vs baseline: 1.0320x; 1.0320x over previous
#include <cuda_runtime.h>
#include <cstdint>

// B=4, H=256, W=256 torus. mu-subsystem only. Persistent kernel, f32x2
// packed (lane = column pair). 128 blocks (1/SM) x 512 thr; 16 warps x
// (5 rows x 64 cols). Region 80r x 64c, interior 64r x 32c, T=8,
// 13 periods (12x8 + 4). Per-iteration sync: PAIRWISE NAMED BARRIERS
// between vertically adjacent warps (id w, 64 threads) - no block-wide
// barrier in the hot loop.
#define BHW 262144
#define NBLOCKS 128

typedef unsigned long long ull;

__device__ float  g_mu[2][BHW];
__device__ float  g_v [2][BHW];
__device__ float4 g_c [BHW];          // 0.01*(ex, ey, eu0, el1)
__device__ float2 g_ac[BHW];          // 0.01*(2*uw1, uw2*y)
__device__ unsigned g_bar;

// ---------------- packed f32x2 helpers ----------------
__device__ __forceinline__ ull pk(float lo, float hi) {
    ull r; asm("mov.b64 %0, {%1, %2};" : "=l"(r) : "f"(lo), "f"(hi)); return r;
}
__device__ __forceinline__ void upk(ull a, float& lo, float& hi) {
    asm("mov.b64 {%0, %1}, %2;" : "=f"(lo), "=f"(hi) : "l"(a));
}
__device__ __forceinline__ ull fma2(ull a, ull b, ull c) {
    ull d; asm("fma.rn.f32x2 %0, %1, %2, %3;" : "=l"(d) : "l"(a), "l"(b), "l"(c)); return d;
}
__device__ __forceinline__ ull add2(ull a, ull b) {
    ull d; asm("add.rn.f32x2 %0, %1, %2;" : "=l"(d) : "l"(a), "l"(b)); return d;
}
__device__ __forceinline__ ull clip2(ull a) {
    float lo, hi; upk(a, lo, hi);
    lo = fminf(fmaxf(lo, 0.0f), 63.0f);
    hi = fminf(fmaxf(hi, 0.0f), 63.0f);
    return pk(lo, hi);
}

#define K07 0x3F3333333F333333ULL   // (0.7f, 0.7f)

// ---------------- init ----------------
__global__ __launch_bounds__(256) void init_kernel(const float* __restrict__ y,
                                                   const float2* __restrict__ ew2,
                                                   const float2* __restrict__ un2) {
    const int p = blockIdx.x * 256 + threadIdx.x;
    const int base = p & ~65535;
    const int i    = p &  65535;
    const int row  = i & ~255;
    const int pu = base | ((i + 65280) & 65535);
    const int pl = base | row | ((i + 255) & 255);

    const float yv = y[p];
    const float2 e  = ew2[p];
    const float  eu = ew2[pu].x;
    const float  el = ew2[pl].y;
    const float2 u  = un2[p];

    g_mu[0][p] = yv;
    g_v [0][p] = 0.0f;
    g_c [p]    = make_float4(0.01f * e.x, 0.01f * e.y, 0.01f * eu, 0.01f * el);
    g_ac[p]    = make_float2(0.01f * 2.0f * u.x, 0.01f * u.y * yv);
    if (p == 0) g_bar = 0u;
}

// ---------------- persistent kernel ----------------
__global__ __launch_bounds__(512, 1) void persist_kernel(float* __restrict__ out) {
    __shared__ ull s_top[2][16][32];     // warp row-0 mu pairs, double-buffered
    __shared__ ull s_bot[2][16][32];     // warp row-4 mu pairs

    const int lane = threadIdx.x & 31;
    const int w    = threadIdx.x >> 5;            // band 0..15 (5 rows each)
    const int blk  = blockIdx.x;                  // 4 img x 4 vtile x 8 htile
    const int base = (blk >> 5) << 16;
    const int tv   = (blk >> 3) & 3;
    const int th   = blk & 7;
    const int gc0  = (th * 32 - 16 + 2 * lane) & 255;   // even; pair never wraps
    const int r0   = tv * 64 - 8 + w * 5;

    // Packed per-row state. cz2[r] == cx2[r-1]; row 0 needs explicit cz0_2.
    ull mu2[5], v2[5], cx2[5], cy2[5], cw2[5], ax2[5], ay2[5], cz0_2;

    #pragma unroll
    for (int r = 0; r < 5; ++r) {
        const int p0 = base + (((r0 + r) & 255) << 8) + gc0;
        mu2[r] = *(const ull*)&g_mu[0][p0];
        v2[r]  = *(const ull*)&g_v[0][p0];
        const float4 c0 = g_c[p0], c1 = g_c[p0 + 1];
        cx2[r] = pk(c0.x, c1.x);
        cy2[r] = pk(c0.y, c1.y);
        cw2[r] = pk(c0.w, c1.w);
        if (r == 0) cz0_2 = pk(c0.z, c1.z);
        const float2 a0 = g_ac[p0], a1 = g_ac[p0 + 1];
        ax2[r] = pk(a0.x, a1.x);
        ay2[r] = pk(a0.y, a1.y);
    }
    __syncthreads();

    unsigned target = 0;

    for (int per = 0; per < 13; ++per) {
        const int TT = (per < 12) ? 8 : 4;

        for (int it = 0; it < TT; ++it) {
            const int rb = it & 1;

            // Publish own old boundary rows for this iteration.
            s_top[rb][w][lane] = mu2[0];
            s_bot[rb][w][lane] = mu2[4];

            // Pairwise sync with vertical neighbor warps (lower id first).
            // Chain is acyclic -> deadlock-free; BAR.SYNC drains the STS.
            if (w > 0)  asm volatile("bar.sync %0, 64;" :: "r"(w)     : "memory");
            if (w < 15) asm volatile("bar.sync %0, 64;" :: "r"(w + 1) : "memory");

            const ull nb_above = (w > 0)  ? s_bot[rb][w - 1][lane] : mu2[0];
            const ull nb_below = (w < 15) ? s_top[rb][w + 1][lane] : mu2[4];

            ull above = nb_above;
            #pragma unroll
            for (int r = 0; r < 5; ++r) {
                const ull cur   = mu2[r];
                const ull below = (r < 4) ? mu2[r + 1] : nb_below;   // old values
                const ull czr   = (r == 0) ? cz0_2 : cx2[r - 1];
                float clo, chi; upk(cur, clo, chi);
                const float phi = __shfl_up_sync(0xFFFFFFFFu, chi, 1);
                const float nlo = __shfl_down_sync(0xFFFFFFFFu, clo, 1);

                ull dmu = fma2(ax2[r], cur, ay2[r]);
                dmu = fma2(cx2[r], below, dmu);
                dmu = fma2(cy2[r], pk(chi, nlo), dmu);
                dmu = fma2(czr,   above, dmu);
                dmu = fma2(cw2[r], pk(phi, clo), dmu);

                v2[r] = fma2(K07, v2[r], dmu);
                above = cur;
                mu2[r] = clip2(add2(cur, v2[r]));
            }
        }

        const int d = (per + 1) & 1;

        // Write exact interior: region rows 8..71, lanes 8..23 (cols 16..47).
        if (lane >= 8 && lane < 24) {
            #pragma unroll
            for (int r = 0; r < 5; ++r) {
                const int R = w * 5 + r;
                if (R >= 8 && R < 72) {
                    const int p0 = base + (((r0 + r) & 255) << 8) + gc0;
                    *(ull*)&g_mu[d][p0] = mu2[r];
                    *(ull*)&g_v [d][p0] = v2[r];
                    if (per == 12) *(ull*)&out[p0] = mu2[r];
                }
            }
        }

        if (per == 12) break;

        // ---- global period barrier (single counter, proven) ----
        __threadfence();
        __syncthreads();
        target += NBLOCKS;
        if (threadIdx.x == 0) {
            atomicAdd(&g_bar, 1u);
            while (*((volatile unsigned*)&g_bar) < target) { }
            __threadfence();
        }
        __syncthreads();

        // Reload halo cells' mu,v (interior stays in registers).
        #pragma unroll
        for (int r = 0; r < 5; ++r) {
            const int R = w * 5 + r;
            const bool interior = (R >= 8) && (R < 72) && (lane >= 8) && (lane < 24);
            if (!interior) {
                const int p0 = base + (((r0 + r) & 255) << 8) + gc0;
                mu2[r] = *(const ull*)&g_mu[d][p0];
                v2[r]  = *(const ull*)&g_v[d][p0];
            }
        }
        __syncthreads();
    }
}

// ---------------- launch ----------------
extern "C" void kernel_launch(void* const* d_in, const int* in_sizes, int n_in,
                              void* d_out, int out_size) {
    const float* y  = (const float*)d_in[0];
    const float* ew = (const float*)d_in[1];
    const float* un = (const float*)d_in[2];
    float* out = (float*)d_out;

    init_kernel<<<1024, 256>>>(y, (const float2*)ew, (const float2*)un);
    persist_kernel<<<NBLOCKS, 512>>>(out);
}